// round 11
// baseline (speedup 1.0000x reference)
#include <cuda_runtime.h>

// out_b = Wp (s_b ∘ (Wq X_b)) + X_b,  s_b[c] = sum_n (Wk X_b)[c,n]*(Wv X_b)[c,n]
// B=2, C=64, N=1024. 128 blocks x 256 threads, one wave.
// Early-arrival schedule: KV GEMM -> s partials -> ARRIVE; then stage Wq/Wp +
// Q GEMM inside the barrier-skew window; wait; minimal post-barrier tail.
// Per-batch barriers (64 arrivals each). Packed fma.rn.f32x2 inner products.

#define NBLK 128
#define NARR 64               // arrivals per (per-batch) barrier
#define NTHR 256
#define WS 68
#define XS 68

#define OFF_WK 0
#define OFF_WV (64 * WS)
#define OFF_WQ (2 * 64 * WS)
#define OFF_WP (3 * 64 * WS)
#define OFF_XT (4 * 64 * WS)
#define OFF_YS (OFF_XT + 16 * XS)
#define OFF_SS (OFF_YS + 16 * XS)
#define SMEM_FLOATS (OFF_SS + 64)

typedef unsigned long long u64;

__device__ float g_sPart[2][64][64];    // [batch][channel][chunk]

__device__ unsigned g_cnt[2];
__device__ volatile unsigned g_flag[2];

__device__ __forceinline__ void fma2(u64& d, u64 a, u64 b) {
    asm("fma.rn.f32x2 %0, %1, %2, %0;" : "+l"(d) : "l"(a), "l"(b));
}
__device__ __forceinline__ u64 mul2(u64 a, u64 b) {
    u64 d;
    asm("mul.rn.f32x2 %0, %1, %2;" : "=l"(d) : "l"(a), "l"(b));
    return d;
}
__device__ __forceinline__ float hsum2(u64 v) {
    float lo, hi;
    asm("mov.b64 {%0, %1}, %2;" : "=f"(lo), "=f"(hi) : "l"(v));
    return lo + hi;
}

extern __shared__ float sm[];

__global__ void __launch_bounds__(NTHR) attn_fused(
    const float* __restrict__ x,
    const float* __restrict__ wq, const float* __restrict__ wk,
    const float* __restrict__ wv, const float* __restrict__ wp,
    float* __restrict__ out)
{
    const int tid = threadIdx.x;
    const int blk = blockIdx.x;
    const int b   = blk >> 6;
    const int ch  = blk & 63;
    const int n0  = ch * 16;

    const int nt = tid & 7;               // column pair: cols nt, nt+8
    const int c0 = (tid >> 3) * 2;        // channel pair

    float* Xs = sm + OFF_XT;
    float* Ys = sm + OFF_YS;
    float* Ss = sm + OFF_SS;

    // ---- Stage Wk, Wv + X chunk --------------------------------------------
    {
        const float* srcs[2] = {wk, wv};
        #pragma unroll
        for (int i = 0; i < 8; i++) {
            const int e  = tid + NTHR * i;        // float4 idx 0..2047
            const int m  = i >> 2;
            const int e2 = e & 1023;
            const int r  = e2 >> 4, c4 = e2 & 15;
            float4 v = ((const float4*)srcs[m])[e2];
            *(float4*)&sm[m * 64 * WS + r * WS + c4 * 4] = v;
        }
        const float* xb = x + b * 65536 + n0;
        #pragma unroll
        for (int i = 0; i < 4; i++) {
            const int e = tid + NTHR * i;         // e = c*16 + n
            Xs[(e & 15) * XS + (e >> 4)] = xb[(e >> 4) * 1024 + (e & 15)];
        }
    }
    __syncthreads();

    // ---- K/V GEMMs -> s partials -------------------------------------------
    {
        const ulonglong2* Wk0 = (const ulonglong2*)&sm[OFF_WK + c0 * WS];
        const ulonglong2* Wk1 = (const ulonglong2*)&sm[OFF_WK + (c0 + 1) * WS];
        const ulonglong2* Wv0 = (const ulonglong2*)&sm[OFF_WV + c0 * WS];
        const ulonglong2* Wv1 = (const ulonglong2*)&sm[OFF_WV + (c0 + 1) * WS];
        const ulonglong2* X0  = (const ulonglong2*)&Xs[nt * XS];
        const ulonglong2* X1  = (const ulonglong2*)&Xs[(nt + 8) * XS];

        u64 K00 = 0, K01 = 0, K10 = 0, K11 = 0;
        u64 V00 = 0, V01 = 0, V10 = 0, V11 = 0;
        #pragma unroll
        for (int jg = 0; jg < 16; jg++) {
            ulonglong2 xa = X0[jg], xb2 = X1[jg];
            ulonglong2 w;
            w = Wk0[jg];
            fma2(K00, w.x, xa.x);  fma2(K00, w.y, xa.y);
            fma2(K01, w.x, xb2.x); fma2(K01, w.y, xb2.y);
            w = Wk1[jg];
            fma2(K10, w.x, xa.x);  fma2(K10, w.y, xa.y);
            fma2(K11, w.x, xb2.x); fma2(K11, w.y, xb2.y);
            w = Wv0[jg];
            fma2(V00, w.x, xa.x);  fma2(V00, w.y, xa.y);
            fma2(V01, w.x, xb2.x); fma2(V01, w.y, xb2.y);
            w = Wv1[jg];
            fma2(V10, w.x, xa.x);  fma2(V10, w.y, xa.y);
            fma2(V11, w.x, xb2.x); fma2(V11, w.y, xb2.y);
        }

        float s0 = hsum2(K00) * hsum2(V00) + hsum2(K01) * hsum2(V01);
        float s1 = hsum2(K10) * hsum2(V10) + hsum2(K11) * hsum2(V11);
        s0 += __shfl_down_sync(0xffffffffu, s0, 4, 8);
        s1 += __shfl_down_sync(0xffffffffu, s1, 4, 8);
        s0 += __shfl_down_sync(0xffffffffu, s0, 2, 8);
        s1 += __shfl_down_sync(0xffffffffu, s1, 2, 8);
        s0 += __shfl_down_sync(0xffffffffu, s0, 1, 8);
        s1 += __shfl_down_sync(0xffffffffu, s1, 1, 8);
        if (nt == 0) {
            g_sPart[b][c0][ch]     = s0;
            g_sPart[b][c0 + 1][ch] = s1;
        }
    }

    // ---- EARLY ARRIVAL (no wait yet) ---------------------------------------
    __syncthreads();                      // all s-partial stores observed in-block
    unsigned f0 = 0;
    if (tid == 0) {
        f0 = g_flag[b];                   // capture BEFORE arriving
        __threadfence();                  // cumulative: publishes block's stores
        unsigned old = atomicAdd(&g_cnt[b], 1u);
        if (old == NARR - 1) {
            g_cnt[b] = 0;                 // reset for next launch/replay
            __threadfence();
            atomicAdd((unsigned*)&g_flag[b], 1u);
        }
    }

    // ---- Inside the skew window: stage Wq/Wp, compute Y = Wq·X -------------
    {
        const float* srcs[2] = {wq, wp};
        #pragma unroll
        for (int i = 0; i < 8; i++) {
            const int e  = tid + NTHR * i;
            const int m  = i >> 2;
            const int e2 = e & 1023;
            const int r  = e2 >> 4, c4 = e2 & 15;
            float4 v = ((const float4*)srcs[m])[e2];
            *(float4*)&sm[(2 + m) * 64 * WS + r * WS + c4 * 4] = v;
        }
    }
    __syncthreads();
    {
        const ulonglong2* Wq0 = (const ulonglong2*)&sm[OFF_WQ + c0 * WS];
        const ulonglong2* Wq1 = (const ulonglong2*)&sm[OFF_WQ + (c0 + 1) * WS];
        const ulonglong2* X0  = (const ulonglong2*)&Xs[nt * XS];
        const ulonglong2* X1  = (const ulonglong2*)&Xs[(nt + 8) * XS];

        u64 Q00 = 0, Q01 = 0, Q10 = 0, Q11 = 0;
        #pragma unroll
        for (int jg = 0; jg < 16; jg++) {
            ulonglong2 xa = X0[jg], xb2 = X1[jg];
            ulonglong2 w;
            w = Wq0[jg];
            fma2(Q00, w.x, xa.x);  fma2(Q00, w.y, xa.y);
            fma2(Q01, w.x, xb2.x); fma2(Q01, w.y, xb2.y);
            w = Wq1[jg];
            fma2(Q10, w.x, xa.x);  fma2(Q10, w.y, xa.y);
            fma2(Q11, w.x, xb2.x); fma2(Q11, w.y, xb2.y);
        }
        *(float2*)&Ys[nt * XS + c0]       = make_float2(hsum2(Q00), hsum2(Q10));
        *(float2*)&Ys[(nt + 8) * XS + c0] = make_float2(hsum2(Q01), hsum2(Q11));
    }

    // ---- Now wait for the barrier release ----------------------------------
    if (tid == 0) {
        while (g_flag[b] == f0) { }
        __threadfence();
    }
    __syncthreads();                      // covers Ys visibility + release

    // ---- Reduce s (4 threads/channel, fixed order -> deterministic) --------
    {
        const int c = tid >> 2, q = tid & 3;
        const float4* sp = (const float4*)&g_sPart[b][c][q * 16];
        float v = 0.f;
        #pragma unroll
        for (int j = 0; j < 4; j++) {
            float4 s4 = __ldcg(&sp[j]);
            v += s4.x + s4.y + s4.z + s4.w;
        }
        v += __shfl_down_sync(0xffffffffu, v, 2, 4);
        v += __shfl_down_sync(0xffffffffu, v, 1, 4);
        if (q == 0) Ss[c] = v;
    }
    __syncthreads();

    // ---- out = Wp · (s ∘ Ys) + X  (packed f32x2) ---------------------------
    {
        const ulonglong2* Wp0 = (const ulonglong2*)&sm[OFF_WP + c0 * WS];
        const ulonglong2* Wp1 = (const ulonglong2*)&sm[OFF_WP + (c0 + 1) * WS];
        const ulonglong2* Y0  = (const ulonglong2*)&Ys[nt * XS];
        const ulonglong2* Y1  = (const ulonglong2*)&Ys[(nt + 8) * XS];
        const ulonglong2* S2  = (const ulonglong2*)Ss;

        u64 O00 = 0, O01 = 0, O10 = 0, O11 = 0;
        #pragma unroll
        for (int jg = 0; jg < 16; jg++) {
            ulonglong2 ss = S2[jg];
            ulonglong2 y0 = Y0[jg], y1 = Y1[jg];
            y0.x = mul2(y0.x, ss.x); y0.y = mul2(y0.y, ss.y);
            y1.x = mul2(y1.x, ss.x); y1.y = mul2(y1.y, ss.y);
            ulonglong2 w;
            w = Wp0[jg];
            fma2(O00, w.x, y0.x); fma2(O00, w.y, y0.y);
            fma2(O01, w.x, y1.x); fma2(O01, w.y, y1.y);
            w = Wp1[jg];
            fma2(O10, w.x, y0.x); fma2(O10, w.y, y0.y);
            fma2(O11, w.x, y1.x); fma2(O11, w.y, y1.y);
        }
        float* ob = out + b * 65536 + n0;
        ob[c0 * 1024 + nt]           = hsum2(O00) + Xs[nt * XS + c0];
        ob[c0 * 1024 + nt + 8]       = hsum2(O01) + Xs[(nt + 8) * XS + c0];
        ob[(c0 + 1) * 1024 + nt]     = hsum2(O10) + Xs[nt * XS + c0 + 1];
        ob[(c0 + 1) * 1024 + nt + 8] = hsum2(O11) + Xs[(nt + 8) * XS + c0 + 1];
    }
}

extern "C" void kernel_launch(void* const* d_in, const int* in_sizes, int n_in,
                              void* d_out, int out_size) {
    const float* x  = (const float*)d_in[0];
    const float* wq = (const float*)d_in[1];
    const float* wk = (const float*)d_in[2];
    const float* wv = (const float*)d_in[3];
    const float* wp = (const float*)d_in[4];

    static int smem_set = 0;
    if (!smem_set) {
        cudaFuncSetAttribute(attn_fused, cudaFuncAttributeMaxDynamicSharedMemorySize,
                             SMEM_FLOATS * (int)sizeof(float));
        smem_set = 1;
    }
    attn_fused<<<NBLK, NTHR, SMEM_FLOATS * sizeof(float)>>>(
        x, wq, wk, wv, wp, (float*)d_out);
}